// round 10
// baseline (speedup 1.0000x reference)
#include <cuda_runtime.h>
#include <cuda_fp8.h>
#include <cuda_fp16.h>
#include <cstdint>
#include <math.h>

#define Bn 8
#define Tn 256
#define Vn 32
#define Dn 256
#define CVT_BLOCKS 128          // must fit in one wave even at occ 1 (152 SMs)
#define MAIN_CTAS 8192          // 2 qt * 2 kt * 32 v * 64 ij  (R9 bug: was 4096)

// ---------------- device scratch (allocation-free) ----------------
__device__ float g_an[Bn * Tn];
__device__ float g_ap[Bn * Tn];
__device__ uint8_t g_fb8 [Bn * Tn * Vn * Dn];   // e4m3 feature      (x32)
__device__ uint8_t g_fab8[Bn * Tn * Vn * Dn];   // e4m3 feature_aug  (x32)
__device__ unsigned g_cntV[Vn];                  // per-v release counters
__device__ unsigned g_done;                      // CTA completion counter

// ---------------- PTX helpers (baseline ISA, sm_89/90 features) ----------------
__device__ __forceinline__ uint32_t smem_to_u32(const void* p) {
    uint32_t a;
    asm("{ .reg .u64 t; cvta.to.shared.u64 t, %1; cvt.u32.u64 %0, t; }"
        : "=r"(a) : "l"(p));
    return a;
}
#define CP_ASYNC16(saddr, gptr) \
    asm volatile("cp.async.cg.shared.global [%0], [%1], 16;" :: "r"(saddr), "l"(gptr))
#define CP_COMMIT() asm volatile("cp.async.commit_group;")
#define CP_WAIT0()  asm volatile("cp.async.wait_group 0;")
#define LDMATRIX_X4(r, addr) \
    asm volatile("ldmatrix.sync.aligned.m8n8.x4.shared.b16 {%0,%1,%2,%3}, [%4];" \
        : "=r"((r)[0]), "=r"((r)[1]), "=r"((r)[2]), "=r"((r)[3]) : "r"(addr))
#define MMA_FP8_F16(d, a, b0, b1) \
    asm volatile("mma.sync.aligned.m16n8k32.row.col.f16.e4m3.e4m3.f16 " \
        "{%0,%1}, {%2,%3,%4,%5}, {%6,%7}, {%0,%1};" \
        : "+r"((d)[0]), "+r"((d)[1]) \
        : "r"((a)[0]), "r"((a)[1]), "r"((a)[2]), "r"((a)[3]), "r"(b0), "r"(b1))

// ---------------- layout ----------------
#define A_BYTES 32768
#define B_BYTES 32768
#define SMEM_DYN (A_BYTES + B_BYTES)   // 64 KB -> 2 CTAs/SM

// ---------------- fused kernel ----------------
// Block t (linear): qt=t&1, kt=(t>>1)&1, v=(t>>2)&31, ij=t>>7 (i=ij>>3, j=ij&7).
// Blocks 0..CVT_BLOCKS-1 first convert fp32 -> e4m3 (x32) per-v and release flags.
__global__ void __launch_bounds__(256, 2) infonce_fused_kernel(
    const float* __restrict__ f, const float* __restrict__ fa, float* __restrict__ out)
{
    extern __shared__ char smem[];
    __shared__ float s_red[128];
    __shared__ unsigned s_old;

    const uint32_t aBase = smem_to_u32(smem);
    const uint32_t bBase = aBase + A_BYTES;
    const int tid  = threadIdx.x;
    const int wid  = tid >> 5;
    const int lane = tid & 31;
    const int warp_m = wid >> 1;
    const int warp_n = wid & 1;

    const int t  = blockIdx.x;
    const int qt = t & 1;
    const int kt = (t >> 1) & 1;
    const int v  = (t >> 2) & 31;
    const int ij = t >> 7;          // 0..63
    const int i  = ij >> 3;
    const int j  = ij & 7;
    const bool diag = (i == j);

    // ---- phase 0: converter blocks (always fully inside wave 1) ----
    if (t < CVT_BLOCKS) {
        // zero accumulators (blocks 0..7), finished before any flag is set
        { int z = t * 256 + tid; if (z < Bn * Tn) { g_an[z] = 0.f; g_ap[z] = 0.f; } }

        // per-v slice: 2 arrays * 2048 (b,t) rows * 64 float4 = 262144 float4
        for (int vv = 0; vv < Vn; vv++) {
            for (int u = t * 256 + tid; u < 262144; u += CVT_BLOCKS * 256) {
                int arr = u >> 17;            // 0: f, 1: fa
                int rem = u & 131071;
                int bt  = rem >> 6;           // 0..2047
                int f4  = rem & 63;           // float4 within d-row
                size_t eidx = ((size_t)(bt * Vn + vv)) * Dn + f4 * 4;
                const float* src = (arr ? fa : f) + eidx;
                float4 x = *(const float4*)src;
                x.x *= 32.f; x.y *= 32.f; x.z *= 32.f; x.w *= 32.f;
                uint32_t* dst = (uint32_t*)(arr ? g_fab8 : g_fb8);
                dst[eidx >> 2] = __nv_fp8x4_e4m3(x).__x;
            }
            __threadfence();
            __syncthreads();
            if (tid == 0) {
                unsigned r;
                asm volatile("atom.release.gpu.global.add.u32 %0, [%1], 1;"
                             : "=r"(r) : "l"(&g_cntV[vv]) : "memory");
            }
        }
    }

    // ---- phase 1: wait until this tile's v-slice is converted ----
    if (tid == 0) {
        unsigned x;
        do {
            asm volatile("ld.acquire.gpu.global.u32 %0, [%1];"
                         : "=r"(x) : "l"(&g_cntV[v]) : "memory");
            if (x < CVT_BLOCKS) __nanosleep(64);
        } while (x < CVT_BLOCKS);
    }
    __syncthreads();

    if (tid < 128) s_red[tid] = 0.f;

    // ---- phase 2: fp8 MMA tile (R7 proven body) ----
    const size_t RS = (size_t)Vn * Dn;
    const uint8_t* Ag = g_fb8  + ((size_t)(i * Tn + qt * 128) * Vn + v) * Dn;
    const uint8_t* Bg = g_fab8 + ((size_t)(j * Tn + kt * 128) * Vn + v) * Dn;

    #pragma unroll
    for (int it = 0; it < 8; it++) {
        int id = tid + it * 256;
        int row = id >> 4, c = id & 15;
        uint32_t soff = (uint32_t)(row * 256) + (uint32_t)((c * 16) ^ ((row & 7) << 4));
        CP_ASYNC16(aBase + soff, Ag + (size_t)row * RS + c * 16);
    }
    #pragma unroll
    for (int it = 0; it < 8; it++) {
        int id = tid + it * 256;
        int row = id >> 4, c = id & 15;
        uint32_t soff = (uint32_t)(row * 256) + (uint32_t)((c * 16) ^ ((row & 7) << 4));
        CP_ASYNC16(bBase + soff, Bg + (size_t)row * RS + c * 16);
    }
    CP_COMMIT();

    uint32_t acc[2][8][2];
    #pragma unroll
    for (int tm = 0; tm < 2; tm++)
        #pragma unroll
        for (int g = 0; g < 8; g++) { acc[tm][g][0] = 0u; acc[tm][g][1] = 0u; }

    CP_WAIT0();
    __syncthreads();

    #pragma unroll
    for (int kk = 0; kk < 8; kk++) {
        uint32_t afr[2][4];
        #pragma unroll
        for (int tm = 0; tm < 2; tm++) {
            int r = warp_m * 32 + tm * 16 + (lane & 7) + ((lane >> 3) & 1) * 8;
            uint32_t kb = (uint32_t)(kk * 32 + ((lane >> 4) & 1) * 16);
            LDMATRIX_X4(afr[tm], aBase + r * 256 + (kb ^ ((r & 7) << 4)));
        }
        #pragma unroll
        for (int gg = 0; gg < 4; gg++) {
            uint32_t bfr[4];
            int n = warp_n * 64 + gg * 16 + (lane & 7) + ((lane >> 4) & 1) * 8;
            uint32_t kb = (uint32_t)(kk * 32 + ((lane >> 3) & 1) * 16);
            LDMATRIX_X4(bfr, bBase + n * 256 + (kb ^ ((n & 7) << 4)));
            #pragma unroll
            for (int tm = 0; tm < 2; tm++) {
                MMA_FP8_F16(acc[tm][gg * 2],     afr[tm], bfr[0], bfr[1]);
                MMA_FP8_F16(acc[tm][gg * 2 + 1], afr[tm], bfr[2], bfr[3]);
            }
        }
    }

    // ---- phase 3: descale, exp, reductions ----
    const float DS = 1.f / 1024.f;

    if (!diag) {
        #pragma unroll
        for (int tm = 0; tm < 2; tm++) {
            float rs0 = 0.f, rs1 = 0.f;
            #pragma unroll
            for (int g = 0; g < 8; g++) {
                float2 e0 = __half22float2(*(const __half2*)&acc[tm][g][0]);
                float2 e1 = __half22float2(*(const __half2*)&acc[tm][g][1]);
                rs0 += __expf(e0.x * DS) + __expf(e0.y * DS);
                rs1 += __expf(e1.x * DS) + __expf(e1.y * DS);
            }
            rs0 += __shfl_xor_sync(0xffffffffu, rs0, 1);
            rs0 += __shfl_xor_sync(0xffffffffu, rs0, 2);
            rs1 += __shfl_xor_sync(0xffffffffu, rs1, 1);
            rs1 += __shfl_xor_sync(0xffffffffu, rs1, 2);
            if ((lane & 3) == 0) {
                int r = warp_m * 32 + tm * 16 + (lane >> 2);
                atomicAdd(&s_red[r], rs0);
                atomicAdd(&s_red[r + 8], rs1);
            }
        }
        __syncthreads();
        if (tid < 128) atomicAdd(&g_an[i * Tn + qt * 128 + tid], s_red[tid]);
    } else {
        #pragma unroll
        for (int g = 0; g < 8; g++) {
            float2 a00 = __half22float2(*(const __half2*)&acc[0][g][0]);
            float2 a01 = __half22float2(*(const __half2*)&acc[0][g][1]);
            float2 a10 = __half22float2(*(const __half2*)&acc[1][g][0]);
            float2 a11 = __half22float2(*(const __half2*)&acc[1][g][1]);
            float cs0 = __expf(a00.x * DS) + __expf(a01.x * DS)
                      + __expf(a10.x * DS) + __expf(a11.x * DS);
            float cs1 = __expf(a00.y * DS) + __expf(a01.y * DS)
                      + __expf(a10.y * DS) + __expf(a11.y * DS);
            cs0 += __shfl_xor_sync(0xffffffffu, cs0, 4);
            cs0 += __shfl_xor_sync(0xffffffffu, cs0, 8);
            cs0 += __shfl_xor_sync(0xffffffffu, cs0, 16);
            cs1 += __shfl_xor_sync(0xffffffffu, cs1, 4);
            cs1 += __shfl_xor_sync(0xffffffffu, cs1, 8);
            cs1 += __shfl_xor_sync(0xffffffffu, cs1, 16);
            if (lane < 4) {
                int c = warp_n * 64 + g * 8 + lane * 2;
                atomicAdd(&s_red[c], cs0);
                atomicAdd(&s_red[c + 1], cs1);
            }
        }
        __syncthreads();
        if (tid < 128) atomicAdd(&g_ap[i * Tn + kt * 128 + tid], s_red[tid]);
    }

    // ---- phase 4: fused loss — last CTA reduces and resets counters ----
    __syncthreads();
    if (tid == 0) {
        __threadfence();
        s_old = atomicAdd(&g_done, 1u);
    }
    __syncthreads();
    if (s_old == MAIN_CTAS - 1) {
        __threadfence();   // visibility of all g_an/g_ap updates
        float s = 0.f;
        for (int idx = tid; idx < Bn * Tn; idx += 256)
            s += logf(g_an[idx]) - logf(g_ap[idx]);
        float* red = (float*)smem;   // reuse dynamic smem (MMA done)
        red[tid] = s;
        __syncthreads();
        for (int m = 128; m > 0; m >>= 1) {
            if (tid < m) red[tid] += red[tid + m];
            __syncthreads();
        }
        if (tid == 0) {
            out[0] = red[0] / (float)Tn;
            g_done = 0;
            #pragma unroll
            for (int k = 0; k < Vn; k++) g_cntV[k] = 0;   // reset for graph replay
        }
    }
}

// ---------------- launch ----------------
extern "C" void kernel_launch(void* const* d_in, const int* in_sizes, int n_in,
                              void* d_out, int out_size) {
    const float* f  = (const float*)d_in[0];
    const float* fa = (const float*)d_in[1];

    cudaFuncSetAttribute(infonce_fused_kernel,
                         cudaFuncAttributeMaxDynamicSharedMemorySize, SMEM_DYN);
    infonce_fused_kernel<<<MAIN_CTAS, 256, SMEM_DYN>>>(f, fa, (float*)d_out);
}

// round 11
// speedup vs baseline: 1.2996x; 1.2996x over previous
#include <cuda_runtime.h>
#include <cuda_fp8.h>
#include <cuda_fp16.h>
#include <cstdint>
#include <math.h>

#define Bn 8
#define Tn 256
#define Vn 32
#define Dn 256

// ---------------- device scratch (allocation-free) ----------------
__device__ float g_an[Bn * Tn];
__device__ float g_ap[Bn * Tn];
__device__ uint8_t g_fb8 [Bn * Tn * Vn * Dn];   // e4m3 feature      (x32)
__device__ uint8_t g_fab8[Bn * Tn * Vn * Dn];   // e4m3 feature_aug  (x32)

// ---------------- PTX helpers (baseline ISA, sm_89/90 features) ----------------
__device__ __forceinline__ uint32_t smem_to_u32(const void* p) {
    uint32_t a;
    asm("{ .reg .u64 t; cvta.to.shared.u64 t, %1; cvt.u32.u64 %0, t; }"
        : "=r"(a) : "l"(p));
    return a;
}
#define CP_ASYNC16(saddr, gptr) \
    asm volatile("cp.async.cg.shared.global [%0], [%1], 16;" :: "r"(saddr), "l"(gptr))
#define CP_COMMIT() asm volatile("cp.async.commit_group;")
#define CP_WAIT0()  asm volatile("cp.async.wait_group 0;")
#define LDMATRIX_X4(r, addr) \
    asm volatile("ldmatrix.sync.aligned.m8n8.x4.shared.b16 {%0,%1,%2,%3}, [%4];" \
        : "=r"((r)[0]), "=r"((r)[1]), "=r"((r)[2]), "=r"((r)[3]) : "r"(addr))
#define MMA_FP8_F16(d, a, b0, b1) \
    asm volatile("mma.sync.aligned.m16n8k32.row.col.f16.e4m3.e4m3.f16 " \
        "{%0,%1}, {%2,%3,%4,%5}, {%6,%7}, {%0,%1};" \
        : "+r"((d)[0]), "+r"((d)[1]) \
        : "r"((a)[0]), "r"((a)[1]), "r"((a)[2]), "r"((a)[3]), "r"(b0), "r"(b1))

// ---------------- layout ----------------
#define A_BYTES 32768
#define B_BYTES 32768
#define SMEM_DYN (A_BYTES + B_BYTES)   // 64 KB -> 2 CTAs/SM (512 thr -> 32 warps/SM)

// ---------------- kernels ----------------
__global__ void cvt_kernel(const float* __restrict__ f, const float* __restrict__ fa) {
    int idx = blockIdx.x * blockDim.x + threadIdx.x;
    const int N4 = Bn * Tn * Vn * Dn / 4;
    if (idx < N4) {
        float4 a = ((const float4*)f)[idx];
        float4 b = ((const float4*)fa)[idx];
        a.x *= 32.f; a.y *= 32.f; a.z *= 32.f; a.w *= 32.f;
        b.x *= 32.f; b.y *= 32.f; b.z *= 32.f; b.w *= 32.f;
        ((uint32_t*)g_fb8 )[idx] = __nv_fp8x4_e4m3(a).__x;
        ((uint32_t*)g_fab8)[idx] = __nv_fp8x4_e4m3(b).__x;
    }
    if (idx < Bn * Tn) { g_an[idx] = 0.f; g_ap[idx] = 0.f; }
}

// One CTA (512 thr, 16 warps, warp tile 32x32):
// S[128,128] = A[128,256] @ B[128,256]^T (fp8 x32, f16 accum), exp(S/1024), reduce.
__global__ void __launch_bounds__(512, 2) infonce_fp8w_kernel() {
    extern __shared__ char smem[];
    __shared__ float s_red[128];

    const uint32_t aBase = smem_to_u32(smem);
    const uint32_t bBase = aBase + A_BYTES;
    const int tid  = threadIdx.x;
    const int wid  = tid >> 5;
    const int lane = tid & 31;
    const int warp_m = wid >> 2;   // 0..3 -> m*32
    const int warp_n = wid & 3;    // 0..3 -> n*32

    const int qt = blockIdx.x & 1;
    const int kt = blockIdx.x >> 1;
    const int v  = blockIdx.y;
    const int i  = blockIdx.z >> 3;
    const int j  = blockIdx.z & 7;
    const bool diag = (i == j);

    if (tid < 128) s_red[tid] = 0.f;

    const size_t RS = (size_t)Vn * Dn;
    const uint8_t* Ag = g_fb8  + ((size_t)(i * Tn + qt * 128) * Vn + v) * Dn;
    const uint8_t* Bg = g_fab8 + ((size_t)(j * Tn + kt * 128) * Vn + v) * Dn;

    // ---- load full tiles: 2048 16B chunks each, swizzled rows of 256B ----
    #pragma unroll
    for (int it = 0; it < 4; it++) {
        int id = tid + it * 512;
        int row = id >> 4, c = id & 15;
        uint32_t soff = (uint32_t)(row * 256) + (uint32_t)((c * 16) ^ ((row & 7) << 4));
        CP_ASYNC16(aBase + soff, Ag + (size_t)row * RS + c * 16);
    }
    #pragma unroll
    for (int it = 0; it < 4; it++) {
        int id = tid + it * 512;
        int row = id >> 4, c = id & 15;
        uint32_t soff = (uint32_t)(row * 256) + (uint32_t)((c * 16) ^ ((row & 7) << 4));
        CP_ASYNC16(bBase + soff, Bg + (size_t)row * RS + c * 16);
    }
    CP_COMMIT();

    // f16 accumulators: [tm][g: 4 n8-blocks][2 b32]
    uint32_t acc[2][4][2];
    #pragma unroll
    for (int tm = 0; tm < 2; tm++)
        #pragma unroll
        for (int g = 0; g < 4; g++) { acc[tm][g][0] = 0u; acc[tm][g][1] = 0u; }

    CP_WAIT0();
    __syncthreads();

    // ---- 8 k-steps of 32 fp8 each ----
    #pragma unroll
    for (int kk = 0; kk < 8; kk++) {
        uint32_t afr[2][4];
        #pragma unroll
        for (int tm = 0; tm < 2; tm++) {
            int r = warp_m * 32 + tm * 16 + (lane & 7) + ((lane >> 3) & 1) * 8;
            uint32_t kb = (uint32_t)(kk * 32 + ((lane >> 4) & 1) * 16);
            LDMATRIX_X4(afr[tm], aBase + r * 256 + (kb ^ ((r & 7) << 4)));
        }
        #pragma unroll
        for (int gg = 0; gg < 2; gg++) {
            uint32_t bfr[4];
            int n = warp_n * 32 + gg * 16 + (lane & 7) + ((lane >> 4) & 1) * 8;
            uint32_t kb = (uint32_t)(kk * 32 + ((lane >> 3) & 1) * 16);
            LDMATRIX_X4(bfr, bBase + n * 256 + (kb ^ ((n & 7) << 4)));
            #pragma unroll
            for (int tm = 0; tm < 2; tm++) {
                MMA_FP8_F16(acc[tm][gg * 2],     afr[tm], bfr[0], bfr[1]);
                MMA_FP8_F16(acc[tm][gg * 2 + 1], afr[tm], bfr[2], bfr[3]);
            }
        }
    }

    // ---- epilogue: unpack f16, descale, exp, reductions ----
    // acc[tm][g]: reg0 = cols (c0,c0+1) @ row r0 = warp_m*32+tm*16+lane/4
    //             reg1 = same cols @ row r0+8
    //             c0 = warp_n*32 + g*8 + (lane&3)*2
    const float DS = 1.f / 1024.f;

    if (!diag) {
        #pragma unroll
        for (int tm = 0; tm < 2; tm++) {
            float rs0 = 0.f, rs1 = 0.f;
            #pragma unroll
            for (int g = 0; g < 4; g++) {
                float2 e0 = __half22float2(*(const __half2*)&acc[tm][g][0]);
                float2 e1 = __half22float2(*(const __half2*)&acc[tm][g][1]);
                rs0 += __expf(e0.x * DS) + __expf(e0.y * DS);
                rs1 += __expf(e1.x * DS) + __expf(e1.y * DS);
            }
            rs0 += __shfl_xor_sync(0xffffffffu, rs0, 1);
            rs0 += __shfl_xor_sync(0xffffffffu, rs0, 2);
            rs1 += __shfl_xor_sync(0xffffffffu, rs1, 1);
            rs1 += __shfl_xor_sync(0xffffffffu, rs1, 2);
            if ((lane & 3) == 0) {
                int r = warp_m * 32 + tm * 16 + (lane >> 2);
                atomicAdd(&s_red[r], rs0);
                atomicAdd(&s_red[r + 8], rs1);
            }
        }
        __syncthreads();
        if (tid < 128) atomicAdd(&g_an[i * Tn + qt * 128 + tid], s_red[tid]);
    } else {
        #pragma unroll
        for (int g = 0; g < 4; g++) {
            float2 a00 = __half22float2(*(const __half2*)&acc[0][g][0]);
            float2 a01 = __half22float2(*(const __half2*)&acc[0][g][1]);
            float2 a10 = __half22float2(*(const __half2*)&acc[1][g][0]);
            float2 a11 = __half22float2(*(const __half2*)&acc[1][g][1]);
            float cs0 = __expf(a00.x * DS) + __expf(a01.x * DS)
                      + __expf(a10.x * DS) + __expf(a11.x * DS);
            float cs1 = __expf(a00.y * DS) + __expf(a01.y * DS)
                      + __expf(a10.y * DS) + __expf(a11.y * DS);
            cs0 += __shfl_xor_sync(0xffffffffu, cs0, 4);
            cs0 += __shfl_xor_sync(0xffffffffu, cs0, 8);
            cs0 += __shfl_xor_sync(0xffffffffu, cs0, 16);
            cs1 += __shfl_xor_sync(0xffffffffu, cs1, 4);
            cs1 += __shfl_xor_sync(0xffffffffu, cs1, 8);
            cs1 += __shfl_xor_sync(0xffffffffu, cs1, 16);
            if (lane < 4) {
                int c = warp_n * 32 + g * 8 + lane * 2;
                atomicAdd(&s_red[c], cs0);
                atomicAdd(&s_red[c + 1], cs1);
            }
        }
        __syncthreads();
        if (tid < 128) atomicAdd(&g_ap[i * Tn + kt * 128 + tid], s_red[tid]);
    }
}

__global__ void loss_kernel(float* out) {
    __shared__ float red[256];
    int tid = threadIdx.x;
    float s = 0.f;
    for (int idx = tid; idx < Bn * Tn; idx += 256)
        s += logf(g_an[idx]) - logf(g_ap[idx]);
    red[tid] = s;
    __syncthreads();
    for (int m = 128; m > 0; m >>= 1) {
        if (tid < m) red[tid] += red[tid + m];
        __syncthreads();
    }
    if (tid == 0) out[0] = red[0] / (float)Tn;
}

// ---------------- launch ----------------
extern "C" void kernel_launch(void* const* d_in, const int* in_sizes, int n_in,
                              void* d_out, int out_size) {
    const float* f  = (const float*)d_in[0];
    const float* fa = (const float*)d_in[1];

    cvt_kernel<<<(Bn * Tn * Vn * Dn / 4 + 255) / 256, 256>>>(f, fa);

    cudaFuncSetAttribute(infonce_fp8w_kernel,
                         cudaFuncAttributeMaxDynamicSharedMemorySize, SMEM_DYN);
    dim3 grid(4, Vn, Bn * Bn);   // (qt + 2*kt, v, i*8+j)
    infonce_fp8w_kernel<<<grid, 512, SMEM_DYN>>>();

    loss_kernel<<<1, 256>>>((float*)d_out);
}